// round 1
// baseline (speedup 1.0000x reference)
#include <cuda_runtime.h>
#include <math_constants.h>

#define SEQ  4096
#define HID  768
#define NB   8
#define KH   385   // HID/2 + 1 (Hermitian half + Nyquist)
#define KM   (HID - KH)   // 383 mirrored bins

// Intermediate spectrum Y[b][k][s] (complex), then overwritten in-place by
// stage B1's twiddled sub-DFT output. 8*385*4096 float2 = ~101 MB.
__device__ float2 g_Y[NB * KH * SEQ];
__device__ float2 g_w12[12 * 12];     // e^{-2pi i h1 r / 12}
__device__ float2 g_w64[64 * 64];     // e^{-2pi i a b / 64}
__device__ float2 g_tw[64 * 64];      // e^{-2pi i a b / 4096}

// ---------------------------------------------------------------- init tables
__global__ void k_init() {
    int i = blockIdx.x * blockDim.x + threadIdx.x;
    if (i < 144) {
        int h1 = i / 12, r = i - h1 * 12;
        float s, c;
        sincospif(-2.0f * (float)(h1 * r) / 12.0f, &s, &c);
        g_w12[i] = make_float2(c, s);
    }
    if (i < 4096) {
        int a = i >> 6, b = i & 63;
        float s, c;
        sincospif(-2.0f * (float)(a * b) / 64.0f, &s, &c);
        g_w64[i] = make_float2(c, s);
        sincospif(-(float)(a * b) / 2048.0f, &s, &c);   // -2*a*b/4096 in pi units
        g_tw[i] = make_float2(c, s);
    }
}

// ------------------------------------------------- stage A: hidden-dim DFT(768)
// 768 = 64 x 12.  G[h0][r] = sum_{h1<12} x[h0+64*h1] * W12^{h1 r}
// Y[k] = sum_{h0<64} G[h0][k%12] * W768^{h0 k},   k = 0..384
// 4 rows per block; writes Y transposed to [b][k][s] so stage B reads coalesced.
__global__ __launch_bounds__(256) void k_stageA(const float* __restrict__ x) {
    __shared__ float  sx[4 * HID];    // 12 KB
    __shared__ float2 sG[4 * HID];    // 24 KB  [row][h0*12+r]
    int rowBase = blockIdx.x * 4;             // over b*SEQ + s
    int b    = rowBase >> 12;
    int srow = rowBase & 4095;
    const float* xp = x + (size_t)rowBase * HID;
    for (int i = threadIdx.x; i < 4 * HID; i += 256) sx[i] = xp[i];
    __syncthreads();

    for (int e = threadIdx.x; e < 4 * HID; e += 256) {
        int row = e / HID;
        int idx = e - row * HID;
        int h0 = idx / 12, r = idx - h0 * 12;
        float gr = 0.f, gi = 0.f;
        #pragma unroll
        for (int h1 = 0; h1 < 12; h1++) {
            float v = sx[row * HID + h0 + 64 * h1];
            float2 w = g_w12[h1 * 12 + r];
            gr = fmaf(v, w.x, gr);
            gi = fmaf(v, w.y, gi);
        }
        sG[e] = make_float2(gr, gi);
    }
    __syncthreads();

    const float NEG2PI_768 = -2.0f * CUDART_PI_F / 768.0f;
    for (int k = threadIdx.x; k < KH; k += 256) {
        int r = k % 12;
        float yr[4] = {0.f, 0.f, 0.f, 0.f};
        float yi[4] = {0.f, 0.f, 0.f, 0.f};
        for (int h0 = 0; h0 < 64; h0++) {
            int p = (h0 * k) % 768;           // exact int reduction -> |angle| <= 2pi
            float sn, cs;
            __sincosf(NEG2PI_768 * (float)p, &sn, &cs);
            #pragma unroll
            for (int row = 0; row < 4; row++) {
                float2 g = sG[row * HID + h0 * 12 + r];
                yr[row] = fmaf(g.x, cs, fmaf(-g.y, sn, yr[row]));
                yi[row] = fmaf(g.x, sn, fmaf( g.y, cs, yi[row]));
            }
        }
        #pragma unroll
        for (int row = 0; row < 4; row++) {
            size_t o = ((size_t)(b * KH + k)) * SEQ + (srow + row);
            g_Y[o] = make_float2(yr[row], yi[row]);
        }
    }
}

// --------------------------------------- stage B1: seq DFT part 1 (64-pt + twiddle)
// s = s0 + 64*s1, m = m0 + 64*m1.
// A[s0][m0] = sum_{s1} y[s0+64 s1] * W64^{s1 m0};  B = A * W4096^{s0 m0}
// In-place per column: safe because the whole column is staged in smem first.
__global__ __launch_bounds__(256) void k_stageB1() {
    __shared__ float2 sy[SEQ];   // 32 KB
    size_t base = (size_t)blockIdx.x * SEQ;   // blockIdx.x = b*KH + k
    for (int i = threadIdx.x; i < SEQ; i += 256) sy[i] = g_Y[base + i];
    __syncthreads();
    for (int o = threadIdx.x; o < SEQ; o += 256) {
        int s0 = o >> 6, m0 = o & 63;
        float ar = 0.f, ai = 0.f;
        #pragma unroll 8
        for (int s1 = 0; s1 < 64; s1++) {
            float2 y = sy[s0 + (s1 << 6)];        // warp-broadcast
            float2 w = g_w64[(s1 << 6) + m0];     // coalesced, L1-hot
            ar = fmaf(y.x, w.x, fmaf(-y.y, w.y, ar));
            ai = fmaf(y.x, w.y, fmaf( y.y, w.x, ai));
        }
        float2 t = g_tw[o];                        // o == s0*64 + m0
        g_Y[base + o] = make_float2(fmaf(ar, t.x, -ai * t.y),
                                    fmaf(ar, t.y,  ai * t.x));
    }
}

// --------------------------------------- stage B2: seq DFT part 2, real part only
// Re(Z[m0 + 64*m1]) = sum_{s0} ( Br[s0][m0]*c - Bi[s0][m0]*s ),  w = W64^{s0 m1}
__global__ __launch_bounds__(256) void k_stageB2(float* __restrict__ out) {
    __shared__ float2 sb[SEQ];   // 32 KB
    int col = blockIdx.x;
    int b = col / KH, k = col - b * KH;
    size_t base = (size_t)col * SEQ;
    for (int i = threadIdx.x; i < SEQ; i += 256) sb[i] = g_Y[base + i];
    __syncthreads();
    for (int m = threadIdx.x; m < SEQ; m += 256) {
        int m0 = m & 63, m1 = m >> 6;
        float zr = 0.f;
        #pragma unroll 8
        for (int s0 = 0; s0 < 64; s0++) {
            float2 bb = sb[(s0 << 6) + m0];       // coalesced in smem
            float2 w  = g_w64[(s0 << 6) + m1];    // warp-broadcast
            zr = fmaf(bb.x, w.x, fmaf(-bb.y, w.y, zr));
        }
        out[((size_t)b * SEQ + m) * HID + k] = zr;
    }
}

// ------------------------------------------------ mirror: fill k = 385..767
// Re(Z[b, m, k]) = Re(Z[b, (S-m)%S, HID-k])
__global__ void k_mirror(float* __restrict__ out) {
    int i = blockIdx.x * blockDim.x + threadIdx.x;
    int total = NB * SEQ * KM;
    if (i >= total) return;
    int j = i % KM;               // 0..382
    int t = i / KM;
    int m = t & 4095;
    int b = t >> 12;
    int k = KH + j;               // 385..767
    int ms = (SEQ - m) & 4095;
    out[((size_t)b * SEQ + m) * HID + k] =
        out[((size_t)b * SEQ + ms) * HID + (HID - k)];
}

extern "C" void kernel_launch(void* const* d_in, const int* in_sizes, int n_in,
                              void* d_out, int out_size) {
    (void)in_sizes; (void)n_in; (void)out_size;
    const float* x = (const float*)d_in[0];
    float* out = (float*)d_out;

    k_init   <<<16, 256>>>();                    // 4096 threads cover all tables
    k_stageA <<<NB * SEQ / 4, 256>>>(x);         // 8192 blocks
    k_stageB1<<<NB * KH, 256>>>();               // 3080 blocks
    k_stageB2<<<NB * KH, 256>>>(out);            // 3080 blocks
    int total = NB * SEQ * KM;
    k_mirror <<<(total + 255) / 256, 256>>>(out);
}

// round 3
// speedup vs baseline: 1.2928x; 1.2928x over previous
#include <cuda_runtime.h>
#include <math_constants.h>

#define SEQ  4096
#define HID  768
#define NB   8
#define KH   385   // HID/2 + 1 (Hermitian half + Nyquist)
#define KM   (HID - KH)   // 383 mirrored bins

// Intermediate spectrum Y[b][k][s] (complex). 8*385*4096 float2 = ~101 MB.
__device__ float2 g_Y[NB * KH * SEQ];
__device__ float2 g_w12[12 * 12];     // e^{-2pi i h1 r / 12}
__device__ float2 g_w64[64 * 64];     // e^{-2pi i a b / 64}
__device__ float2 g_tw[64 * 64];      // e^{-2pi i a b / 4096}
__device__ float2 g_w768[768];        // e^{-2pi i p / 768}

// ---------------------------------------------------------------- init tables
__global__ void k_init() {
    int i = blockIdx.x * blockDim.x + threadIdx.x;
    if (i < 144) {
        int h1 = i / 12, r = i - h1 * 12;
        float s, c;
        sincospif(-2.0f * (float)(h1 * r) / 12.0f, &s, &c);
        g_w12[i] = make_float2(c, s);
    }
    if (i < 768) {
        float s, c;
        sincospif(-2.0f * (float)i / 768.0f, &s, &c);
        g_w768[i] = make_float2(c, s);
    }
    if (i < 4096) {
        int a = i >> 6, b = i & 63;
        float s, c;
        sincospif(-2.0f * (float)(a * b) / 64.0f, &s, &c);
        g_w64[i] = make_float2(c, s);
        sincospif(-(float)(a * b) / 2048.0f, &s, &c);   // -2*a*b/4096 in pi units
        g_tw[i] = make_float2(c, s);
    }
}

// ------------------------------------------------- stage A: hidden-dim DFT(768)
// 768 = 64 x 12.  G[h0][r] = sum_{h1<12} x[h0+64*h1] * W12^{h1 r}
// Y[k] = sum_{h0<64} G[h0][k%12] * W768^{(h0 k)%768},   k = 0..384
__global__ __launch_bounds__(256) void k_stageA(const float* __restrict__ x) {
    __shared__ float  sx[4 * HID];    // 12 KB
    __shared__ float2 sG[4 * HID];    // 24 KB  [row][h0*12+r]
    int rowBase = blockIdx.x * 4;             // over b*SEQ + s
    int b    = rowBase >> 12;
    int srow = rowBase & 4095;
    const float* xp = x + (size_t)rowBase * HID;
    for (int i = threadIdx.x; i < 4 * HID; i += 256) sx[i] = xp[i];
    __syncthreads();

    for (int e = threadIdx.x; e < 4 * HID; e += 256) {
        int row = e / HID;
        int idx = e - row * HID;
        int h0 = idx / 12, r = idx - h0 * 12;
        float gr = 0.f, gi = 0.f;
        #pragma unroll
        for (int h1 = 0; h1 < 12; h1++) {
            float v = sx[row * HID + h0 + 64 * h1];
            float2 w = __ldg(&g_w12[h1 * 12 + r]);
            gr = fmaf(v, w.x, gr);
            gi = fmaf(v, w.y, gi);
        }
        sG[e] = make_float2(gr, gi);
    }
    __syncthreads();

    for (int k = threadIdx.x; k < KH; k += 256) {
        int r = k % 12;
        float yr[4] = {0.f, 0.f, 0.f, 0.f};
        float yi[4] = {0.f, 0.f, 0.f, 0.f};
        int p = 0;                      // (h0*k) % 768, incremental
        #pragma unroll 8
        for (int h0 = 0; h0 < 64; h0++) {
            float2 w = __ldg(&g_w768[p]);
            p += k; if (p >= 768) p -= 768;     // k <= 384 < 768, exact
            #pragma unroll
            for (int row = 0; row < 4; row++) {
                float2 g = sG[row * HID + h0 * 12 + r];
                yr[row] = fmaf(g.x, w.x, fmaf(-g.y, w.y, yr[row]));
                yi[row] = fmaf(g.x, w.y, fmaf( g.y, w.x, yi[row]));
            }
        }
        #pragma unroll
        for (int row = 0; row < 4; row++) {
            size_t o = ((size_t)(b * KH + k)) * SEQ + (srow + row);
            g_Y[o] = make_float2(yr[row], yi[row]);
        }
    }
}

// --------------------------------------- fused seq-dim FFT(4096) = 64 x 64
// Per block: one (b,k) column of 4096 complex values, staged in smem.
// Stage 1: A[s0][m0] = (sum_{s1} y[s0+64 s1] W64^{s1 m0}) * W4096^{s0 m0}
//          (accumulated in registers, written back to smem in place)
// Stage 2: Re(Z[m0+64 m1]) = sum_{s0} Re(A[s0][m0] * W64^{s0 m1})
// Each thread owns a 4x4 register tile in both stages.
__global__ __launch_bounds__(256) void k_stageB(float* __restrict__ out) {
    __shared__ float2 sy[SEQ];   // 32 KB
    int col = blockIdx.x;                 // b*KH + k
    int b = col / KH, k = col - b * KH;
    size_t base = (size_t)col * SEQ;

    const float4* syv = (const float4*)sy;        // 2 complex per float4
    const float4* gw  = (const float4*)g_w64;

    for (int i = threadIdx.x; i < SEQ; i += 256) sy[i] = g_Y[base + i];
    __syncthreads();

    int t  = threadIdx.x;
    int i0 = (t >> 4) << 2;    // s0 tile base (stage1) / m1 tile base (stage2)
    int j0 = (t & 15) << 2;    // m0 tile base

    // ---- stage 1 ----
    float2 acc[4][4];
    #pragma unroll
    for (int r = 0; r < 4; r++)
        #pragma unroll
        for (int c = 0; c < 4; c++) acc[r][c] = make_float2(0.f, 0.f);

    #pragma unroll 4
    for (int s1 = 0; s1 < 64; s1++) {
        float4 ya = syv[(s1 << 5) + (i0 >> 1)];
        float4 yb = syv[(s1 << 5) + (i0 >> 1) + 1];
        float4 wa = __ldg(&gw[(s1 << 5) + (j0 >> 1)]);
        float4 wb = __ldg(&gw[(s1 << 5) + (j0 >> 1) + 1]);
        float yx[4] = {ya.x, ya.z, yb.x, yb.z};
        float yy[4] = {ya.y, ya.w, yb.y, yb.w};
        float wx[4] = {wa.x, wa.z, wb.x, wb.z};
        float wy[4] = {wa.y, wa.w, wb.y, wb.w};
        #pragma unroll
        for (int r = 0; r < 4; r++)
            #pragma unroll
            for (int c = 0; c < 4; c++) {
                acc[r][c].x = fmaf(yx[r], wx[c], fmaf(-yy[r], wy[c], acc[r][c].x));
                acc[r][c].y = fmaf(yx[r], wy[c], fmaf( yy[r], wx[c], acc[r][c].y));
            }
    }
    __syncthreads();            // all stage-1 reads of sy complete

    #pragma unroll
    for (int r = 0; r < 4; r++)
        #pragma unroll
        for (int c = 0; c < 4; c++) {
            float2 tw = __ldg(&g_tw[(i0 + r) * 64 + (j0 + c)]);
            float2 v = acc[r][c];
            sy[(i0 + r) * 64 + (j0 + c)] =
                make_float2(fmaf(v.x, tw.x, -v.y * tw.y),
                            fmaf(v.x, tw.y,  v.y * tw.x));
        }
    __syncthreads();            // stage-1 writes visible

    // ---- stage 2 (real part only) ----
    int a0 = j0;                // m0 tile base
    int b0 = i0;                // m1 tile base
    float zr[4][4];
    #pragma unroll
    for (int r = 0; r < 4; r++)
        #pragma unroll
        for (int c = 0; c < 4; c++) zr[r][c] = 0.f;

    #pragma unroll 4
    for (int s0 = 0; s0 < 64; s0++) {
        float4 ba = syv[(s0 << 5) + (a0 >> 1)];
        float4 bb = syv[(s0 << 5) + (a0 >> 1) + 1];
        float4 wa = __ldg(&gw[(s0 << 5) + (b0 >> 1)]);
        float4 wb = __ldg(&gw[(s0 << 5) + (b0 >> 1) + 1]);
        float bx[4] = {ba.x, ba.z, bb.x, bb.z};
        float by[4] = {ba.y, ba.w, bb.y, bb.w};
        float wx[4] = {wa.x, wa.z, wb.x, wb.z};
        float wy[4] = {wa.y, wa.w, wb.y, wb.w};
        #pragma unroll
        for (int r = 0; r < 4; r++)
            #pragma unroll
            for (int c = 0; c < 4; c++)
                zr[r][c] = fmaf(bx[r], wx[c], fmaf(-by[r], wy[c], zr[r][c]));
    }

    #pragma unroll
    for (int r = 0; r < 4; r++)
        #pragma unroll
        for (int c = 0; c < 4; c++) {
            int m = (a0 + r) + ((b0 + c) << 6);
            out[((size_t)b * SEQ + m) * HID + k] = zr[r][c];
        }
}

// ------------------------------------------------ mirror: fill k = 385..767
// Re(Z[b, m, k]) = Re(Z[b, (S-m)%S, HID-k])
__global__ void k_mirror(float* __restrict__ out) {
    int i = blockIdx.x * blockDim.x + threadIdx.x;
    int total = NB * SEQ * KM;
    if (i >= total) return;
    int j = i % KM;               // 0..382
    int t = i / KM;
    int m = t & 4095;
    int b = t >> 12;
    int k = KH + j;               // 385..767
    int ms = (SEQ - m) & 4095;
    out[((size_t)b * SEQ + m) * HID + k] =
        out[((size_t)b * SEQ + ms) * HID + (HID - k)];
}

extern "C" void kernel_launch(void* const* d_in, const int* in_sizes, int n_in,
                              void* d_out, int out_size) {
    (void)in_sizes; (void)n_in; (void)out_size;
    const float* x = (const float*)d_in[0];
    float* out = (float*)d_out;

    k_init   <<<16, 256>>>();                    // 4096 threads cover all tables
    k_stageA <<<NB * SEQ / 4, 256>>>(x);         // 8192 blocks
    k_stageB <<<NB * KH, 256>>>(out);            // 3080 blocks, fused B1+B2
    int total = NB * SEQ * KM;
    k_mirror <<<(total + 255) / 256, 256>>>(out);
}